// round 16
// baseline (speedup 1.0000x reference)
#include <cuda_runtime.h>
#include <cuda_fp16.h>
#include <math.h>
#include <stdint.h>

// ---------------- problem constants ----------------
#define B_   2048
#define S_   5
#define N_   80
#define E_   592
#define FX_  8
#define FF_  4
#define FE_  8
#define D_   8
#define H_   800
#define NG_  (B_ * S_)            // 10240 graphs
#define XDIM_ (N_ * D_)           // 640
#define EDIM_ (E_ * D_)           // 4736
#define SEQ_  (XDIM_ + EDIM_)     // 5376 (= 84 * 64)
#define G3H_  (3 * H_)            // 2400
#define G3HP_ 2432                // padded to 19*128
#define HPAD_ 832                 // 800 padded to 13*64
#define YPAD_ 4032                // 4000 padded to 63*64
#define MLP1_ 1280
#define OUTN_ 400                 // S_*80
#define OUTNP_ 512                // padded to 4*128
#define JT_   64                  // j's per fused-GRU tile
#define NJT_  (HPAD_ / JT_)       // 13 j-tiles
#define BR_   (3 * JT_)           // 192 B rows per j-tile
#define NCHK_ 4                   // GNN/gi pipeline chunks
#define CHG_  (NG_ / NCHK_)       // 2560 graphs per chunk

// ---------------- scratch (__device__ globals: allocation-free) ----------------
__device__ __align__(128) __half g_seq16[(size_t)NG_ * SEQ_];
__device__ __align__(128) __half g_wih16[(size_t)G3HP_ * SEQ_];
__device__ __align__(128) __half g_whhG [(size_t)NJT_ * BR_ * HPAD_];
__device__ __align__(128) __half g_w1t16[(size_t)MLP1_ * YPAD_];
__device__ __align__(128) __half g_w2t16[(size_t)OUTNP_ * MLP1_];
__device__ __align__(128) __half g_h16a[(size_t)B_ * HPAD_];
__device__ __align__(128) __half g_h16b[(size_t)B_ * HPAD_];
__device__ __align__(128) __half g_y16[(size_t)B_ * YPAD_];
__device__ __align__(128) __half g_z1 [(size_t)B_ * MLP1_];
__device__ __align__(128) __half g_gi [(size_t)NG_ * G3H_];
__device__ float g_z1f[2 * (size_t)B_ * MLP1_];
__device__ float g_o4 [4 * (size_t)B_ * OUTN_];
__device__ float g_h  [(size_t)B_  * H_];

// ---------------- helpers ----------------
__device__ __forceinline__ uint32_t smem_u32(const void* p) {
    uint32_t a;
    asm("{ .reg .u64 t; cvta.to.shared.u64 t, %1; cvt.u32.u64 %0, t; }"
        : "=r"(a) : "l"(p));
    return a;
}
#define SW128(o) ((o) ^ (((o) >> 3) & 0x70))

__device__ __forceinline__ void cp16(uint32_t dst, const void* src) {
    asm volatile("cp.async.cg.shared.global [%0], [%1], 16;" :: "r"(dst), "l"(src));
}
__device__ __forceinline__ void cp_commit() {
    asm volatile("cp.async.commit_group;");
}
__device__ __forceinline__ void ldm4(uint32_t& r0, uint32_t& r1, uint32_t& r2, uint32_t& r3,
                                     uint32_t addr) {
    asm volatile("ldmatrix.sync.aligned.m8n8.x4.shared.b16 {%0,%1,%2,%3}, [%4];"
                 : "=r"(r0), "=r"(r1), "=r"(r2), "=r"(r3) : "r"(addr));
}
__device__ __forceinline__ void mma16816(float* c, const uint32_t* a, const uint32_t* b) {
    asm volatile(
        "mma.sync.aligned.m16n8k16.row.col.f32.f16.f16.f32 "
        "{%0,%1,%2,%3}, {%4,%5,%6,%7}, {%8,%9}, {%0,%1,%2,%3};"
        : "+f"(c[0]), "+f"(c[1]), "+f"(c[2]), "+f"(c[3])
        : "r"(a[0]), "r"(a[1]), "r"(a[2]), "r"(a[3]), "r"(b[0]), "r"(b[1]));
}
__device__ __forceinline__ float sigm(float v) { return 1.f / (1.f + expf(-v)); }

// ---------------- GNN: CSR-gather, vectorized smem, 4 CTAs/SM ----------------
__global__ void __launch_bounds__(256, 4) gnn_kernel(
    const float* __restrict__ x, const int* __restrict__ edge_index,
    const float* __restrict__ edge_f, const float* __restrict__ edge_attr,
    const float* __restrict__ Wx, const float* __restrict__ We,
    const float* __restrict__ Wf, const float* __restrict__ Wedge,
    __half* __restrict__ seq16, int g0)
{
    const int g = blockIdx.x + g0;
    const int tid = threadIdx.x;

    const float* xg  = x          + (size_t)g * N_ * FX_;
    const int*   ei  = edge_index + (size_t)g * 2 * E_;
    const float* efg = edge_f     + (size_t)g * E_ * FF_;
    const float* eag = edge_attr  + (size_t)g * E_ * FE_;

    __shared__ float sWx[FX_ * D_];
    __shared__ float sWe[FE_ * D_];
    __shared__ float sWf[FF_ * D_];
    __shared__ float sWedge[(2 * D_ + FE_) * D_];
    __shared__ __align__(16) float s_msg[E_ * D_];
    __shared__ __align__(16) float s_eag[E_ * FE_];
    __shared__ __align__(16) float s_xout[N_ * D_];
    __shared__ short s_src[E_];
    __shared__ short s_dst[E_];
    __shared__ short s_perm[E_];
    __shared__ int   s_cnt[128];
    __shared__ int   s_start[129];
    __shared__ int   s_ofs[N_];
    __shared__ int   s_min;

    if (tid < FX_ * D_) sWx[tid] = Wx[tid];
    if (tid < FE_ * D_) sWe[tid] = We[tid];
    if (tid < FF_ * D_) sWf[tid] = Wf[tid];
    if (tid < (2 * D_ + FE_) * D_) sWedge[tid] = Wedge[tid];
    if (tid < 128) s_cnt[tid] = 0;
    if (tid == 0) s_min = 0x7fffffff;
    __syncthreads();

    int lmin = 0x7fffffff;
    for (int e = tid; e < E_; e += 256) lmin = min(lmin, ei[e]);
    atomicMin(&s_min, lmin);

    // stream edge_attr into smem (float4)
    for (int i = tid; i < E_ * FE_ / 4; i += 256)
        *reinterpret_cast<float4*>(&s_eag[i * 4]) =
            *reinterpret_cast<const float4*>(&eag[i * 4]);
    __syncthreads();
    const int mn = s_min;

    // Phase A1: indices + in-degree counts
    for (int e = tid; e < E_; e += 256) {
        int sI = ei[e]      - mn;
        int dI = ei[E_ + e] - mn;
        if (dI < 0) dI += N_;     // JAX negative-index wrap
        s_src[e] = (short)sI;
        s_dst[e] = (short)dI;
        atomicAdd(&s_cnt[dI], 1);
    }
    // Phase A2: edge messages, (e, d-pair) tasks, vector loads
    for (int task = tid; task < E_ * 4; task += 256) {
        const int e  = task >> 2;
        const int dp = (task & 3) << 1;
        float ea[8], ef[4];
        *reinterpret_cast<float4*>(&ea[0]) = *reinterpret_cast<const float4*>(&s_eag[e * 8]);
        *reinterpret_cast<float4*>(&ea[4]) = *reinterpret_cast<const float4*>(&s_eag[e * 8 + 4]);
        *reinterpret_cast<float4*>(&ef[0]) = *reinterpret_cast<const float4*>(&efg[e * 4]);
#pragma unroll
        for (int q = 0; q < 2; q++) {
            const int d = dp + q;
            float m = 0.f;
#pragma unroll
            for (int k = 0; k < FE_; k++) m = fmaf(ea[k], sWe[k * D_ + d], m);
#pragma unroll
            for (int k = 0; k < FF_; k++) m = fmaf(ef[k], sWf[k * D_ + d], m);
            s_msg[e * 8 + d] = fmaxf(m, 0.f);
        }
    }
    __syncthreads();

    // Exclusive scan of s_cnt[0..127] by warp 0
    if (tid < 32) {
        const int v0 = s_cnt[tid * 4 + 0];
        const int v1 = s_cnt[tid * 4 + 1];
        const int v2 = s_cnt[tid * 4 + 2];
        const int v3 = s_cnt[tid * 4 + 3];
        const int s = v0 + v1 + v2 + v3;
        int xinc = s;
#pragma unroll
        for (int off = 1; off < 32; off <<= 1) {
            int y = __shfl_up_sync(0xFFFFFFFFu, xinc, off);
            if (tid >= off) xinc += y;
        }
        const int base = xinc - s;
        s_start[tid * 4 + 0] = base;
        s_start[tid * 4 + 1] = base + v0;
        s_start[tid * 4 + 2] = base + v0 + v1;
        s_start[tid * 4 + 3] = base + v0 + v1 + v2;
        if (tid == 31) s_start[128] = xinc;
    }
    __syncthreads();
    if (tid < N_) s_ofs[tid] = s_start[tid];
    __syncthreads();

    // Phase B: counting-sort edge ids by dst
    for (int e = tid; e < E_; e += 256) {
        int pos = atomicAdd(&s_ofs[(int)s_dst[e]], 1);
        s_perm[pos] = (short)e;
    }
    __syncthreads();

    // Phase C: node update via gather
    for (int task = tid; task < N_ * D_; task += 256) {
        const int n = task >> 3;
        const int d = task & 7;
        float agg = 0.f;
        const int s0 = s_start[n];
        const int s1 = s_start[n + 1];
        for (int i = s0; i < s1; i++)
            agg += s_msg[(int)s_perm[i] * D_ + d];
        float t = agg;
#pragma unroll
        for (int k = 0; k < FX_; k++) t = fmaf(xg[n * FX_ + k], sWx[k * D_ + d], t);
        float xo = xg[n * FX_ + d] + fmaxf(t, 0.f);
        s_xout[n * D_ + d] = xo;
        seq16[(size_t)g * SEQ_ + n * D_ + d] = __float2half_rn(xo);
    }
    __syncthreads();

    // Phase D: edge update, (e, d-pair) tasks, vector loads, half2 stores
    for (int task = tid; task < E_ * 4; task += 256) {
        const int e  = task >> 2;
        const int dp = (task & 3) << 1;
        const int sI = (int)s_src[e], dI = (int)s_dst[e];
        float xs[8], xd[8], ea[8];
        *reinterpret_cast<float4*>(&xs[0]) = *reinterpret_cast<const float4*>(&s_xout[sI * 8]);
        *reinterpret_cast<float4*>(&xs[4]) = *reinterpret_cast<const float4*>(&s_xout[sI * 8 + 4]);
        *reinterpret_cast<float4*>(&xd[0]) = *reinterpret_cast<const float4*>(&s_xout[dI * 8]);
        *reinterpret_cast<float4*>(&xd[4]) = *reinterpret_cast<const float4*>(&s_xout[dI * 8 + 4]);
        *reinterpret_cast<float4*>(&ea[0]) = *reinterpret_cast<const float4*>(&s_eag[e * 8]);
        *reinterpret_cast<float4*>(&ea[4]) = *reinterpret_cast<const float4*>(&s_eag[e * 8 + 4]);
        float o[2];
#pragma unroll
        for (int q = 0; q < 2; q++) {
            const int d = dp + q;
            float t = 0.f;
#pragma unroll
            for (int k = 0; k < D_; k++)  t = fmaf(xs[k], sWedge[k * D_ + d], t);
#pragma unroll
            for (int k = 0; k < D_; k++)  t = fmaf(xd[k], sWedge[(D_ + k) * D_ + d], t);
#pragma unroll
            for (int k = 0; k < FE_; k++) t = fmaf(ea[k], sWedge[(2 * D_ + k) * D_ + d], t);
            o[q] = s_eag[e * 8 + d] + fmaxf(t, 0.f);
        }
        *reinterpret_cast<__half2*>(seq16 + (size_t)g * SEQ_ + XDIM_ + e * 8 + dp) =
            __floats2half2_rn(o[0], o[1]);
    }
}

// ---------------- weight conversions ----------------
#define NB_WIH ((G3HP_ * SEQ_ + 255) / 256)
#define NB_WHG ((NJT_ * BR_ * HPAD_ + 255) / 256)
#define NB_CV  (NB_WIH + NB_WHG)

__global__ void __launch_bounds__(256) conv_direct(
    const float* __restrict__ w_ih, const float* __restrict__ w_hh,
    __half* __restrict__ o_wih, __half* __restrict__ o_whhG)
{
    int b = blockIdx.x;
    if (b < NB_WIH) {
        size_t i = (size_t)b * 256 + threadIdx.x;
        if (i < (size_t)G3HP_ * SEQ_) {
            int n = (int)(i / SEQ_);
            o_wih[i] = __float2half_rn(n < G3H_ ? w_ih[i] : 0.f);
        }
        return;
    }
    b -= NB_WIH;
    {
        size_t i = (size_t)b * 256 + threadIdx.x;
        if (i < (size_t)NJT_ * BR_ * HPAD_) {
            int row = (int)(i / HPAD_);
            int k   = (int)(i % HPAD_);
            int jt  = row / BR_;
            int rr  = row % BR_;
            int comp = rr / JT_;
            int j    = jt * JT_ + (rr % JT_);
            float v = 0.f;
            if (j < H_ && k < H_)
                v = w_hh[(size_t)(comp * H_ + j) * H_ + k];
            o_whhG[i] = __float2half_rn(v);
        }
    }
}

// ---------------- tiled transpose-convert ----------------
__global__ void __launch_bounds__(256) trans_conv(
    const float* __restrict__ src, __half* __restrict__ dst,
    int R, int C, int Dr, int Dc)
{
    __shared__ float tile[32][33];
    const int j0 = blockIdx.x * 32;
    const int i0 = blockIdx.y * 32;
    const int tx = threadIdx.x & 31;
    const int ty = threadIdx.x >> 5;

    for (int r = ty; r < 32; r += 8) {
        float v = 0.f;
        const int j = j0 + r, i = i0 + tx;
        if (j < R && i < C) v = src[(size_t)j * C + i];
        tile[r][tx] = v;
    }
    __syncthreads();
    for (int r = ty; r < 32; r += 8) {
        const int i = i0 + r, j = j0 + tx;
        if (i < Dr && j < Dc)
            dst[(size_t)i * Dc + j] = __float2half_rn(tile[tx][r]);
    }
}

// ---------------- HMMA TN GEMM, templated M-tile, 3-stage, split-K ----------------
template <bool OUTH, int MT>
__global__ void __launch_bounds__(256, 2) gemm_f16(
    const __half* __restrict__ A, const __half* __restrict__ Bw,
    const float* __restrict__ bias,
    float* __restrict__ C, __half* __restrict__ Ch,
    int M, int Nn, int K, int nchz)
{
    constexpr int TOFF_B = MT * 128;
    constexpr int TSTAGE = TOFF_B + 16384;
    constexpr int MW  = MT / 32;
    constexpr int NWN = 8 / MW;
    constexpr int NSL = 128 / NWN;
    constexpr int NS  = NSL / 8;
    constexpr int TPR = 256 / MT;
    constexpr int APT = MT / 32;

    const int z = blockIdx.z;
    const int ch0 = z * nchz;
    const int nch = min(nchz, K / 64 - ch0);
    if (nch <= 0) return;
    A  += ch0 * 64;
    Bw += ch0 * 64;
    const bool dob = (z == 0);

    extern __shared__ char smem[];
    const uint32_t sbase = smem_u32(smem);
    const int tid = threadIdx.x;
    const int wid = tid >> 5, lid = tid & 31;
    const int m0 = blockIdx.y * MT;
    const int n0 = blockIdx.x * 128;

    const int wm = wid % MW;
    const int wn = wid / MW;

    float acc[2][NS][4];
#pragma unroll
    for (int i = 0; i < 2; i++)
#pragma unroll
        for (int j = 0; j < NS; j++)
#pragma unroll
            for (int q = 0; q < 4; q++) acc[i][j][q] = 0.f;

    const int lrowA = tid / TPR;
    const int ckA0  = (tid % TPR) * APT;
    const int lrowB = tid >> 1;
    const int ckB0  = (tid & 1) * 4;

    auto load_stage = [&](int st, int c) {
        const int k0 = c * 64;
        const uint32_t stb = sbase + st * TSTAGE;
#pragma unroll
        for (int i = 0; i < APT; i++) {
            const int kc = ckA0 + i;
            const uint32_t so = SW128((uint32_t)(lrowA * 128 + kc * 16));
            cp16(stb + so, A + (size_t)(m0 + lrowA) * K + k0 + kc * 8);
        }
#pragma unroll
        for (int i = 0; i < 4; i++) {
            const int kc = ckB0 + i;
            const uint32_t so = SW128((uint32_t)(lrowB * 128 + kc * 16));
            cp16(stb + TOFF_B + so, Bw + (size_t)(n0 + lrowB) * K + k0 + kc * 8);
        }
        cp_commit();
    };

    load_stage(0, 0);
    if (nch > 1) load_stage(1, 1);

    const int lt = lid >> 3;
    const int lr = lid & 7;

    int st = 0;
    for (int c = 0; c < nch; c++) {
        if (c + 1 < nch) asm volatile("cp.async.wait_group 1;");
        else             asm volatile("cp.async.wait_group 0;");
        __syncthreads();

        if (c + 2 < nch) load_stage((st + 2) % 3, c + 2);

        const uint32_t stb = sbase + st * TSTAGE;
#pragma unroll
        for (int kk = 0; kk < 4; kk++) {
            const int kc = kk * 2 + (lt >> 1);
            uint32_t aH[2][4];
#pragma unroll
            for (int mt = 0; mt < 2; mt++) {
                const int row = wm * 32 + mt * 16 + (lt & 1) * 8 + lr;
                const uint32_t so = SW128((uint32_t)(row * 128 + kc * 16));
                ldm4(aH[mt][0], aH[mt][1], aH[mt][2], aH[mt][3], stb + so);
            }
            uint32_t bf[NS][2];
#pragma unroll
            for (int nt = 0; nt < NS / 2; nt++) {
                const int row = wn * NSL + nt * 16 + (lt & 1) * 8 + lr;
                const uint32_t so = SW128((uint32_t)(row * 128 + kc * 16));
                uint32_t q0, q1, q2, q3;
                ldm4(q0, q1, q2, q3, stb + TOFF_B + so);
                bf[nt * 2][0] = q0; bf[nt * 2][1] = q2;
                bf[nt * 2 + 1][0] = q1; bf[nt * 2 + 1][1] = q3;
            }
#pragma unroll
            for (int mt = 0; mt < 2; mt++)
#pragma unroll
                for (int ns = 0; ns < NS; ns++)
                    mma16816(acc[mt][ns], aH[mt], bf[ns]);
        }
        st = (st + 1) % 3;
    }

    float* Cz = C + (size_t)z * M * Nn;
    __half* Chz = Ch + (size_t)z * M * Nn;
    const int gq = lid >> 2;
    const int tq = lid & 3;
#pragma unroll
    for (int mt = 0; mt < 2; mt++) {
#pragma unroll
        for (int ns = 0; ns < NS; ns++) {
            const int col = n0 + wn * NSL + ns * 8 + tq * 2;
            const int r0 = m0 + wm * 32 + mt * 16 + gq;
            if (col < Nn) {
                const float b0 = dob ? bias[col] : 0.f;
                const float b1 = dob ? bias[col + 1] : 0.f;
                if (OUTH) {
                    __half2 v0 = __floats2half2_rn(acc[mt][ns][0] + b0, acc[mt][ns][1] + b1);
                    __half2 v1 = __floats2half2_rn(acc[mt][ns][2] + b0, acc[mt][ns][3] + b1);
                    *reinterpret_cast<__half2*>(Chz + (size_t)r0 * Nn + col)       = v0;
                    *reinterpret_cast<__half2*>(Chz + (size_t)(r0 + 8) * Nn + col) = v1;
                } else {
                    float2 v0 = make_float2(acc[mt][ns][0] + b0, acc[mt][ns][1] + b1);
                    float2 v1 = make_float2(acc[mt][ns][2] + b0, acc[mt][ns][3] + b1);
                    *reinterpret_cast<float2*>(Cz + (size_t)r0 * Nn + col)       = v0;
                    *reinterpret_cast<float2*>(Cz + (size_t)(r0 + 8) * Nn + col) = v1;
                }
            }
        }
    }
}

// ---------------- FUSED gh GEMM + GRU gate (t >= 1), ping-pong h16 ----------------
__global__ void __launch_bounds__(256, 2) gemm_gru_fused(
    const __half* __restrict__ h_in,
    const __half* __restrict__ BwG,
    const float* __restrict__ b_hh,
    const __half* __restrict__ gi_all,
    float* __restrict__ h, __half* __restrict__ h_out, __half* __restrict__ y16,
    int t)
{
    constexpr int TOFF_B = 8192;
    constexpr int TSTAGE = 8192 + 24576;
    constexpr int NCH = HPAD_ / 64;

    extern __shared__ char smem[];
    const uint32_t sbase = smem_u32(smem);
    const int tid = threadIdx.x;
    const int wid = tid >> 5, lid = tid & 31;
    const int jt = blockIdx.x;
    const int m0 = blockIdx.y * 64;

    const __half* Bw = BwG + (size_t)jt * BR_ * HPAD_;

    const int wm = wid & 1;
    const int wj = wid >> 1;

    float acc[2][6][4];
#pragma unroll
    for (int i = 0; i < 2; i++)
#pragma unroll
        for (int j = 0; j < 6; j++)
#pragma unroll
            for (int q = 0; q < 4; q++) acc[i][j][q] = 0.f;

    auto load_stage = [&](int st, int c) {
        const int k0 = c * 64;
        const uint32_t stb = sbase + st * TSTAGE;
#pragma unroll
        for (int i = 0; i < 2; i++) {
            const int o = tid + 256 * i;
            const int row = o >> 3, kc = o & 7;
            const uint32_t so = SW128((uint32_t)(row * 128 + kc * 16));
            cp16(stb + so, h_in + (size_t)(m0 + row) * HPAD_ + k0 + kc * 8);
        }
#pragma unroll
        for (int i = 0; i < 6; i++) {
            const int o = tid + 256 * i;
            const int row = o >> 3, kc = o & 7;
            const uint32_t so = SW128((uint32_t)(row * 128 + kc * 16));
            cp16(stb + TOFF_B + so, Bw + (size_t)row * HPAD_ + k0 + kc * 8);
        }
        cp_commit();
    };

    load_stage(0, 0);
    load_stage(1, 1);

    const int lt = lid >> 3;
    const int lr = lid & 7;

    int st = 0;
    for (int c = 0; c < NCH; c++) {
        if (c + 1 < NCH) asm volatile("cp.async.wait_group 1;");
        else             asm volatile("cp.async.wait_group 0;");
        __syncthreads();

        if (c + 2 < NCH) load_stage((st + 2) % 3, c + 2);

        const uint32_t stb = sbase + st * TSTAGE;
#pragma unroll
        for (int kk = 0; kk < 4; kk++) {
            const int kc = kk * 2 + (lt >> 1);
            uint32_t aH[2][4];
#pragma unroll
            for (int mt = 0; mt < 2; mt++) {
                const int row = wm * 32 + mt * 16 + (lt & 1) * 8 + lr;
                const uint32_t so = SW128((uint32_t)(row * 128 + kc * 16));
                ldm4(aH[mt][0], aH[mt][1], aH[mt][2], aH[mt][3], stb + so);
            }
            uint32_t bf[6][2];
#pragma unroll
            for (int comp = 0; comp < 3; comp++) {
                const int row = comp * 64 + wj * 16 + (lt & 1) * 8 + lr;
                const uint32_t so = SW128((uint32_t)(row * 128 + kc * 16));
                uint32_t q0, q1, q2, q3;
                ldm4(q0, q1, q2, q3, stb + TOFF_B + so);
                bf[comp * 2][0] = q0; bf[comp * 2][1] = q2;
                bf[comp * 2 + 1][0] = q1; bf[comp * 2 + 1][1] = q3;
            }
#pragma unroll
            for (int mt = 0; mt < 2; mt++)
#pragma unroll
                for (int ns = 0; ns < 6; ns++)
                    mma16816(acc[mt][ns], aH[mt], bf[ns]);
        }
        st = (st + 1) % 3;
    }

    const int gq = lid >> 2;
    const int tq = lid & 3;
#pragma unroll
    for (int mt = 0; mt < 2; mt++) {
#pragma unroll
        for (int k = 0; k < 2; k++) {
            const int j = jt * JT_ + wj * 16 + k * 8 + tq * 2;
            if (j >= H_) continue;
            const float br0 = b_hh[j],          br1 = b_hh[j + 1];
            const float bz0 = b_hh[H_ + j],     bz1 = b_hh[H_ + j + 1];
            const float bn0 = b_hh[2 * H_ + j], bn1 = b_hh[2 * H_ + j + 1];
            const int r0 = m0 + wm * 32 + mt * 16 + gq;
#pragma unroll
            for (int rr = 0; rr < 2; rr++) {
                const int row = r0 + rr * 8;
                const __half* gi = gi_all + (size_t)(row * S_ + t) * G3H_;
                const float2 gir = __half22float2(*reinterpret_cast<const __half2*>(gi + j));
                const float2 giz = __half22float2(*reinterpret_cast<const __half2*>(gi + H_ + j));
                const float2 gin = __half22float2(*reinterpret_cast<const __half2*>(gi + 2 * H_ + j));
                const float2 hp  = *reinterpret_cast<const float2*>(h + (size_t)row * H_ + j);

                const float hr0 = acc[mt][0 + k][rr * 2]     + br0;
                const float hr1 = acc[mt][0 + k][rr * 2 + 1] + br1;
                const float hz0 = acc[mt][2 + k][rr * 2]     + bz0;
                const float hz1 = acc[mt][2 + k][rr * 2 + 1] + bz1;
                const float hn0 = acc[mt][4 + k][rr * 2]     + bn0;
                const float hn1 = acc[mt][4 + k][rr * 2 + 1] + bn1;

                const float rg0 = sigm(gir.x + hr0), rg1 = sigm(gir.y + hr1);
                const float zg0 = sigm(giz.x + hz0), zg1 = sigm(giz.y + hz1);
                const float ng0 = tanhf(gin.x + rg0 * hn0), ng1 = tanhf(gin.y + rg1 * hn1);
                const float h0 = (1.f - zg0) * ng0 + zg0 * hp.x;
                const float h1 = (1.f - zg1) * ng1 + zg1 * hp.y;

                *reinterpret_cast<float2*>(h + (size_t)row * H_ + j) = make_float2(h0, h1);
                const __half2 hv = __floats2half2_rn(h0, h1);
                *reinterpret_cast<__half2*>(h_out + (size_t)row * HPAD_ + j) = hv;
                *reinterpret_cast<__half2*>(y16 + (size_t)row * YPAD_ + t * H_ + j) = hv;
            }
        }
    }
}

// ---------------- GRU gate for t=0 only ----------------
__global__ void __launch_bounds__(256) gru_gate0(
    const __half* __restrict__ gi_all, const float* __restrict__ gh_bias,
    float* __restrict__ h, __half* __restrict__ h16, __half* __restrict__ y16)
{
    const int idx2 = blockIdx.x * blockDim.x + threadIdx.x;
    if (idx2 >= B_ * (H_ / 2)) return;
    const int b = idx2 / (H_ / 2);
    const int j = (idx2 % (H_ / 2)) * 2;

    const __half* gi = gi_all + (size_t)(b * S_) * G3H_;
    const float2 ir2 = __half22float2(*reinterpret_cast<const __half2*>(gi + j));
    const float2 iz2 = __half22float2(*reinterpret_cast<const __half2*>(gi + H_ + j));
    const float2 in2 = __half22float2(*reinterpret_cast<const __half2*>(gi + 2 * H_ + j));
    const float2 hr2 = *reinterpret_cast<const float2*>(gh_bias + j);
    const float2 hz2 = *reinterpret_cast<const float2*>(gh_bias + H_ + j);
    const float2 hn2 = *reinterpret_cast<const float2*>(gh_bias + 2 * H_ + j);

    const float r0 = sigm(ir2.x + hr2.x), r1 = sigm(ir2.y + hr2.y);
    const float z0 = sigm(iz2.x + hz2.x), z1 = sigm(iz2.y + hz2.y);
    const float n0 = tanhf(in2.x + r0 * hn2.x), n1 = tanhf(in2.y + r1 * hn2.y);
    const float h0 = (1.f - z0) * n0;
    const float h1 = (1.f - z1) * n1;

    *reinterpret_cast<float2*>(h + (size_t)b * H_ + j) = make_float2(h0, h1);
    const __half2 hv = __floats2half2_rn(h0, h1);
    *reinterpret_cast<__half2*>(h16 + (size_t)b * HPAD_ + j) = hv;
    *reinterpret_cast<__half2*>(y16 + (size_t)b * YPAD_ + j) = hv;
}

// ---------------- partial sums ----------------
__global__ void __launch_bounds__(256) add2h_kernel(
    const float* __restrict__ p, __half* __restrict__ z1)
{
    const int i = blockIdx.x * 256 + threadIdx.x;
    if (i >= B_ * MLP1_) return;
    const size_t st = (size_t)B_ * MLP1_;
    z1[i] = __float2half_rn(p[i] + p[st + i]);
}
__global__ void __launch_bounds__(256) add4_kernel(
    const float* __restrict__ p, float* __restrict__ out)
{
    const int i = blockIdx.x * 256 + threadIdx.x;
    if (i >= B_ * OUTN_) return;
    const size_t st = (size_t)B_ * OUTN_;
    out[i] = p[i] + p[st + i] + p[2 * st + i] + p[3 * st + i];
}

// ---------------- launch ----------------
extern "C" void kernel_launch(void* const* d_in, const int* in_sizes, int n_in,
                              void* d_out, int out_size)
{
    const float* x          = (const float*)d_in[0];
    const int*   edge_index = (const int*)  d_in[1];
    const float* edge_f     = (const float*)d_in[2];
    const float* edge_attr  = (const float*)d_in[3];
    const float* Wx         = (const float*)d_in[4];
    const float* We         = (const float*)d_in[5];
    const float* Wf         = (const float*)d_in[6];
    const float* Wedge      = (const float*)d_in[7];
    const float* w_ih       = (const float*)d_in[8];
    const float* w_hh       = (const float*)d_in[9];
    const float* b_ih       = (const float*)d_in[10];
    const float* b_hh       = (const float*)d_in[11];
    const float* mlp_w1     = (const float*)d_in[12];
    const float* mlp_b1     = (const float*)d_in[13];
    const float* mlp_w2     = (const float*)d_in[14];
    const float* mlp_b2     = (const float*)d_in[15];
    float* out = (float*)d_out;

    __half *p_seq, *p_wih, *p_whhG, *p_w1t, *p_w2t, *p_h16a, *p_h16b, *p_y16, *p_z1, *p_gi;
    float *p_z1f, *p_o4, *p_h;
    cudaGetSymbolAddress((void**)&p_seq,  g_seq16);
    cudaGetSymbolAddress((void**)&p_wih,  g_wih16);
    cudaGetSymbolAddress((void**)&p_whhG, g_whhG);
    cudaGetSymbolAddress((void**)&p_w1t,  g_w1t16);
    cudaGetSymbolAddress((void**)&p_w2t,  g_w2t16);
    cudaGetSymbolAddress((void**)&p_h16a, g_h16a);
    cudaGetSymbolAddress((void**)&p_h16b, g_h16b);
    cudaGetSymbolAddress((void**)&p_y16,  g_y16);
    cudaGetSymbolAddress((void**)&p_z1,   g_z1);
    cudaGetSymbolAddress((void**)&p_gi,   g_gi);
    cudaGetSymbolAddress((void**)&p_z1f,  g_z1f);
    cudaGetSymbolAddress((void**)&p_o4,   g_o4);
    cudaGetSymbolAddress((void**)&p_h,    g_h);

    const int SM64  = 3 * (64 * 128 + 16384);    // 73728
    const int SM128 = 3 * (128 * 128 + 16384);   // 98304
    const int SMFU  = 3 * (8192 + 24576);        // 98304

    cudaFuncSetAttribute((const void*)gemm_f16<true, 128>,
                         cudaFuncAttributeMaxDynamicSharedMemorySize, SM128);
    cudaFuncSetAttribute((const void*)gemm_f16<false, 64>,
                         cudaFuncAttributeMaxDynamicSharedMemorySize, SM64);
    cudaFuncSetAttribute((const void*)gemm_f16<false, 128>,
                         cudaFuncAttributeMaxDynamicSharedMemorySize, SM128);
    cudaFuncSetAttribute((const void*)gemm_gru_fused,
                         cudaFuncAttributeMaxDynamicSharedMemorySize, SMFU);

    // streams + events (host-side, created once; no device alloc)
    static cudaStream_t s1 = nullptr, s2 = nullptr;
    static cudaEvent_t evFork = nullptr, evJoin = nullptr, evG[NCHK_];
    if (s1 == nullptr) {
        cudaStreamCreateWithFlags(&s1, cudaStreamNonBlocking);
        cudaStreamCreateWithFlags(&s2, cudaStreamNonBlocking);
        cudaEventCreateWithFlags(&evFork, cudaEventDisableTiming);
        cudaEventCreateWithFlags(&evJoin, cudaEventDisableTiming);
        for (int c = 0; c < NCHK_; c++)
            cudaEventCreateWithFlags(&evG[c], cudaEventDisableTiming);
    }

    // fork
    cudaEventRecord(evFork, 0);
    cudaStreamWaitEvent(s1, evFork, 0);
    cudaStreamWaitEvent(s2, evFork, 0);

    // s1: memsets + weight conversions
    cudaMemsetAsync(p_h16a, 0, sizeof(__half) * B_ * HPAD_, s1);
    cudaMemsetAsync(p_h16b, 0, sizeof(__half) * B_ * HPAD_, s1);
    cudaMemsetAsync(p_y16, 0, sizeof(__half) * B_ * YPAD_, s1);
    conv_direct<<<NB_CV, 256, 0, s1>>>(w_ih, w_hh, p_wih, p_whhG);
    {
        dim3 gt1((YPAD_ + 31) / 32, MLP1_ / 32);
        trans_conv<<<gt1, 256, 0, s1>>>(mlp_w1, p_w1t, S_ * H_, MLP1_, MLP1_, YPAD_);
        dim3 gt2((MLP1_ + 31) / 32, OUTNP_ / 32);
        trans_conv<<<gt2, 256, 0, s1>>>(mlp_w2, p_w2t, MLP1_, OUTN_, OUTNP_, MLP1_);
    }
    cudaEventRecord(evJoin, s1);

    // s2: GNN in chunks, event per chunk
    for (int c = 0; c < NCHK_; c++) {
        gnn_kernel<<<CHG_, 256, 0, s2>>>(x, edge_index, edge_f, edge_attr,
                                         Wx, We, Wf, Wedge, p_seq, c * CHG_);
        cudaEventRecord(evG[c], s2);
    }

    // stream 0: gi chunk-by-chunk, overlapping later GNN chunks
    cudaStreamWaitEvent(0, evJoin, 0);   // gi needs w_ih; rest needs conversions
    for (int c = 0; c < NCHK_; c++) {
        cudaStreamWaitEvent(0, evG[c], 0);
        dim3 grid(G3HP_ / 128, CHG_ / 128, 1);   // 19 x 20
        gemm_f16<true, 128><<<grid, 256, SM128>>>(
            p_seq + (size_t)c * CHG_ * SEQ_, p_wih, b_ih,
            nullptr, p_gi + (size_t)c * CHG_ * G3H_, CHG_, G3H_, SEQ_, 84);
    }

    // 3) GRU: t=0 pointwise -> h16a; t>=1 fused with ping-pong h16 buffers
    gru_gate0<<<(B_ * (H_ / 2) + 255) / 256, 256>>>(p_gi, b_hh, p_h, p_h16a, p_y16);
    {
        dim3 gridf(NJT_, B_ / 64);              // 13 x 32
        __half* bufs[2] = { p_h16a, p_h16b };
        for (int t = 1; t < S_; t++) {
            __half* hin  = bufs[(t - 1) & 1];
            __half* hout = bufs[t & 1];
            gemm_gru_fused<<<gridf, 256, SMFU>>>(hin, p_whhG, b_hh, p_gi,
                                                 p_h, hout, p_y16, t);
        }
    }

    // 4) MLP
    {
        dim3 g1(MLP1_ / 128, B_ / 64, 2);       // mlp1: MT=64, split-K=2
        gemm_f16<false, 64><<<g1, 256, SM64>>>(p_y16, p_w1t, mlp_b1,
                                               p_z1f, nullptr, B_, MLP1_, YPAD_, 32);
        add2h_kernel<<<(B_ * MLP1_ + 255) / 256, 256>>>(p_z1f, p_z1);

        dim3 g2(OUTNP_ / 128, B_ / 128, 4);     // mlp2: MT=128, split-K=4
        gemm_f16<false, 128><<<g2, 256, SM128>>>(p_z1, p_w2t, mlp_b2,
                                                 p_o4, nullptr, B_, OUTN_, MLP1_, 5);
        add4_kernel<<<(B_ * OUTN_ + 255) / 256, 256>>>(p_o4, out);
    }
}

// round 17
// speedup vs baseline: 1.0968x; 1.0968x over previous
#include <cuda_runtime.h>
#include <cuda_fp16.h>
#include <math.h>
#include <stdint.h>

// ---------------- problem constants ----------------
#define B_   2048
#define S_   5
#define N_   80
#define E_   592
#define FX_  8
#define FF_  4
#define FE_  8
#define D_   8
#define H_   800
#define NG_  (B_ * S_)            // 10240 graphs
#define XDIM_ (N_ * D_)           // 640
#define EDIM_ (E_ * D_)           // 4736
#define SEQ_  (XDIM_ + EDIM_)     // 5376 (= 84 * 64)
#define G3H_  (3 * H_)            // 2400
#define G3HP_ 2432                // padded to 19*128
#define HPAD_ 832                 // 800 padded to 13*64
#define YPAD_ 4032                // 4000 padded to 63*64
#define MLP1_ 1280
#define OUTN_ 400                 // S_*80
#define OUTNP_ 512                // padded to 4*128
#define JT_   64                  // j's per fused-GRU tile
#define NJT_  (HPAD_ / JT_)       // 13 j-tiles
#define BR_   (3 * JT_)           // 192 B rows per j-tile
#define NCHK_ 2                   // GNN/gi pipeline chunks (760-CTA gi chunks: no wave waste)
#define CHG_  (NG_ / NCHK_)       // 5120 graphs per chunk

// ---------------- scratch (__device__ globals: allocation-free) ----------------
__device__ __align__(128) __half g_seq16[(size_t)NG_ * SEQ_];
__device__ __align__(128) __half g_wih16[(size_t)G3HP_ * SEQ_];
__device__ __align__(128) __half g_whhG [(size_t)NJT_ * BR_ * HPAD_];
__device__ __align__(128) __half g_w1t16[(size_t)MLP1_ * YPAD_];
__device__ __align__(128) __half g_w2t16[(size_t)OUTNP_ * MLP1_];
__device__ __align__(128) __half g_h16a[(size_t)B_ * HPAD_];
__device__ __align__(128) __half g_h16b[(size_t)B_ * HPAD_];
__device__ __align__(128) __half g_y16[(size_t)B_ * YPAD_];
__device__ __align__(128) __half g_z1 [(size_t)B_ * MLP1_];
__device__ __align__(128) __half g_gi [(size_t)NG_ * G3H_];
__device__ float g_z1f[2 * (size_t)B_ * MLP1_];
__device__ float g_o4 [4 * (size_t)B_ * OUTN_];
__device__ float g_h  [(size_t)B_  * H_];

// ---------------- helpers ----------------
__device__ __forceinline__ uint32_t smem_u32(const void* p) {
    uint32_t a;
    asm("{ .reg .u64 t; cvta.to.shared.u64 t, %1; cvt.u32.u64 %0, t; }"
        : "=r"(a) : "l"(p));
    return a;
}
#define SW128(o) ((o) ^ (((o) >> 3) & 0x70))

__device__ __forceinline__ void cp16(uint32_t dst, const void* src) {
    asm volatile("cp.async.cg.shared.global [%0], [%1], 16;" :: "r"(dst), "l"(src));
}
__device__ __forceinline__ void cp_commit() {
    asm volatile("cp.async.commit_group;");
}
__device__ __forceinline__ void ldm4(uint32_t& r0, uint32_t& r1, uint32_t& r2, uint32_t& r3,
                                     uint32_t addr) {
    asm volatile("ldmatrix.sync.aligned.m8n8.x4.shared.b16 {%0,%1,%2,%3}, [%4];"
                 : "=r"(r0), "=r"(r1), "=r"(r2), "=r"(r3) : "r"(addr));
}
__device__ __forceinline__ void mma16816(float* c, const uint32_t* a, const uint32_t* b) {
    asm volatile(
        "mma.sync.aligned.m16n8k16.row.col.f32.f16.f16.f32 "
        "{%0,%1,%2,%3}, {%4,%5,%6,%7}, {%8,%9}, {%0,%1,%2,%3};"
        : "+f"(c[0]), "+f"(c[1]), "+f"(c[2]), "+f"(c[3])
        : "r"(a[0]), "r"(a[1]), "r"(a[2]), "r"(a[3]), "r"(b[0]), "r"(b[1]));
}
__device__ __forceinline__ float sigm(float v) { return 1.f / (1.f + expf(-v)); }

// ---------------- GNN: CSR-gather, vectorized smem, 4 CTAs/SM ----------------
__global__ void __launch_bounds__(256, 4) gnn_kernel(
    const float* __restrict__ x, const int* __restrict__ edge_index,
    const float* __restrict__ edge_f, const float* __restrict__ edge_attr,
    const float* __restrict__ Wx, const float* __restrict__ We,
    const float* __restrict__ Wf, const float* __restrict__ Wedge,
    __half* __restrict__ seq16, int g0)
{
    const int g = blockIdx.x + g0;
    const int tid = threadIdx.x;

    const float* xg  = x          + (size_t)g * N_ * FX_;
    const int*   ei  = edge_index + (size_t)g * 2 * E_;
    const float* efg = edge_f     + (size_t)g * E_ * FF_;
    const float* eag = edge_attr  + (size_t)g * E_ * FE_;

    __shared__ float sWx[FX_ * D_];
    __shared__ float sWe[FE_ * D_];
    __shared__ float sWf[FF_ * D_];
    __shared__ float sWedge[(2 * D_ + FE_) * D_];
    __shared__ __align__(16) float s_msg[E_ * D_];
    __shared__ __align__(16) float s_eag[E_ * FE_];
    __shared__ __align__(16) float s_xout[N_ * D_];
    __shared__ short s_src[E_];
    __shared__ short s_dst[E_];
    __shared__ short s_perm[E_];
    __shared__ int   s_cnt[128];
    __shared__ int   s_start[129];
    __shared__ int   s_ofs[N_];
    __shared__ int   s_min;

    if (tid < FX_ * D_) sWx[tid] = Wx[tid];
    if (tid < FE_ * D_) sWe[tid] = We[tid];
    if (tid < FF_ * D_) sWf[tid] = Wf[tid];
    if (tid < (2 * D_ + FE_) * D_) sWedge[tid] = Wedge[tid];
    if (tid < 128) s_cnt[tid] = 0;
    if (tid == 0) s_min = 0x7fffffff;
    __syncthreads();

    int lmin = 0x7fffffff;
    for (int e = tid; e < E_; e += 256) lmin = min(lmin, ei[e]);
    atomicMin(&s_min, lmin);

    for (int i = tid; i < E_ * FE_ / 4; i += 256)
        *reinterpret_cast<float4*>(&s_eag[i * 4]) =
            *reinterpret_cast<const float4*>(&eag[i * 4]);
    __syncthreads();
    const int mn = s_min;

    // Phase A1: indices + in-degree counts
    for (int e = tid; e < E_; e += 256) {
        int sI = ei[e]      - mn;
        int dI = ei[E_ + e] - mn;
        if (dI < 0) dI += N_;     // JAX negative-index wrap
        s_src[e] = (short)sI;
        s_dst[e] = (short)dI;
        atomicAdd(&s_cnt[dI], 1);
    }
    // Phase A2: edge messages, (e, d-pair) tasks
    for (int task = tid; task < E_ * 4; task += 256) {
        const int e  = task >> 2;
        const int dp = (task & 3) << 1;
        float ea[8], ef[4];
        *reinterpret_cast<float4*>(&ea[0]) = *reinterpret_cast<const float4*>(&s_eag[e * 8]);
        *reinterpret_cast<float4*>(&ea[4]) = *reinterpret_cast<const float4*>(&s_eag[e * 8 + 4]);
        *reinterpret_cast<float4*>(&ef[0]) = *reinterpret_cast<const float4*>(&efg[e * 4]);
#pragma unroll
        for (int q = 0; q < 2; q++) {
            const int d = dp + q;
            float m = 0.f;
#pragma unroll
            for (int k = 0; k < FE_; k++) m = fmaf(ea[k], sWe[k * D_ + d], m);
#pragma unroll
            for (int k = 0; k < FF_; k++) m = fmaf(ef[k], sWf[k * D_ + d], m);
            s_msg[e * 8 + d] = fmaxf(m, 0.f);
        }
    }
    __syncthreads();

    // Exclusive scan of s_cnt[0..127] by warp 0
    if (tid < 32) {
        const int v0 = s_cnt[tid * 4 + 0];
        const int v1 = s_cnt[tid * 4 + 1];
        const int v2 = s_cnt[tid * 4 + 2];
        const int v3 = s_cnt[tid * 4 + 3];
        const int s = v0 + v1 + v2 + v3;
        int xinc = s;
#pragma unroll
        for (int off = 1; off < 32; off <<= 1) {
            int y = __shfl_up_sync(0xFFFFFFFFu, xinc, off);
            if (tid >= off) xinc += y;
        }
        const int base = xinc - s;
        s_start[tid * 4 + 0] = base;
        s_start[tid * 4 + 1] = base + v0;
        s_start[tid * 4 + 2] = base + v0 + v1;
        s_start[tid * 4 + 3] = base + v0 + v1 + v2;
        if (tid == 31) s_start[128] = xinc;
    }
    __syncthreads();
    if (tid < N_) s_ofs[tid] = s_start[tid];
    __syncthreads();

    // Phase B: counting-sort edge ids by dst
    for (int e = tid; e < E_; e += 256) {
        int pos = atomicAdd(&s_ofs[(int)s_dst[e]], 1);
        s_perm[pos] = (short)e;
    }
    __syncthreads();

    // Phase C: node update via gather
    for (int task = tid; task < N_ * D_; task += 256) {
        const int n = task >> 3;
        const int d = task & 7;
        float agg = 0.f;
        const int s0 = s_start[n];
        const int s1 = s_start[n + 1];
        for (int i = s0; i < s1; i++)
            agg += s_msg[(int)s_perm[i] * D_ + d];
        float t = agg;
#pragma unroll
        for (int k = 0; k < FX_; k++) t = fmaf(xg[n * FX_ + k], sWx[k * D_ + d], t);
        float xo = xg[n * FX_ + d] + fmaxf(t, 0.f);
        s_xout[n * D_ + d] = xo;
        seq16[(size_t)g * SEQ_ + n * D_ + d] = __float2half_rn(xo);
    }
    __syncthreads();

    // Phase D: edge update, (e, d-pair) tasks, vector loads, half2 stores
    for (int task = tid; task < E_ * 4; task += 256) {
        const int e  = task >> 2;
        const int dp = (task & 3) << 1;
        const int sI = (int)s_src[e], dI = (int)s_dst[e];
        float xs[8], xd[8], ea[8];
        *reinterpret_cast<float4*>(&xs[0]) = *reinterpret_cast<const float4*>(&s_xout[sI * 8]);
        *reinterpret_cast<float4*>(&xs[4]) = *reinterpret_cast<const float4*>(&s_xout[sI * 8 + 4]);
        *reinterpret_cast<float4*>(&xd[0]) = *reinterpret_cast<const float4*>(&s_xout[dI * 8]);
        *reinterpret_cast<float4*>(&xd[4]) = *reinterpret_cast<const float4*>(&s_xout[dI * 8 + 4]);
        *reinterpret_cast<float4*>(&ea[0]) = *reinterpret_cast<const float4*>(&s_eag[e * 8]);
        *reinterpret_cast<float4*>(&ea[4]) = *reinterpret_cast<const float4*>(&s_eag[e * 8 + 4]);
        float o[2];
#pragma unroll
        for (int q = 0; q < 2; q++) {
            const int d = dp + q;
            float t = 0.f;
#pragma unroll
            for (int k = 0; k < D_; k++)  t = fmaf(xs[k], sWedge[k * D_ + d], t);
#pragma unroll
            for (int k = 0; k < D_; k++)  t = fmaf(xd[k], sWedge[(D_ + k) * D_ + d], t);
#pragma unroll
            for (int k = 0; k < FE_; k++) t = fmaf(ea[k], sWedge[(2 * D_ + k) * D_ + d], t);
            o[q] = s_eag[e * 8 + d] + fmaxf(t, 0.f);
        }
        *reinterpret_cast<__half2*>(seq16 + (size_t)g * SEQ_ + XDIM_ + e * 8 + dp) =
            __floats2half2_rn(o[0], o[1]);
    }
}

// ---------------- weight conversions ----------------
#define NB_WIH ((G3HP_ * SEQ_ + 255) / 256)
#define NB_WHG ((NJT_ * BR_ * HPAD_ + 255) / 256)
#define NB_CV  (NB_WIH + NB_WHG)

__global__ void __launch_bounds__(256) conv_direct(
    const float* __restrict__ w_ih, const float* __restrict__ w_hh,
    __half* __restrict__ o_wih, __half* __restrict__ o_whhG)
{
    int b = blockIdx.x;
    if (b < NB_WIH) {
        size_t i = (size_t)b * 256 + threadIdx.x;
        if (i < (size_t)G3HP_ * SEQ_) {
            int n = (int)(i / SEQ_);
            o_wih[i] = __float2half_rn(n < G3H_ ? w_ih[i] : 0.f);
        }
        return;
    }
    b -= NB_WIH;
    {
        size_t i = (size_t)b * 256 + threadIdx.x;
        if (i < (size_t)NJT_ * BR_ * HPAD_) {
            int row = (int)(i / HPAD_);
            int k   = (int)(i % HPAD_);
            int jt  = row / BR_;
            int rr  = row % BR_;
            int comp = rr / JT_;
            int j    = jt * JT_ + (rr % JT_);
            float v = 0.f;
            if (j < H_ && k < H_)
                v = w_hh[(size_t)(comp * H_ + j) * H_ + k];
            o_whhG[i] = __float2half_rn(v);
        }
    }
}

// ---------------- tiled transpose-convert ----------------
__global__ void __launch_bounds__(256) trans_conv(
    const float* __restrict__ src, __half* __restrict__ dst,
    int R, int C, int Dr, int Dc)
{
    __shared__ float tile[32][33];
    const int j0 = blockIdx.x * 32;
    const int i0 = blockIdx.y * 32;
    const int tx = threadIdx.x & 31;
    const int ty = threadIdx.x >> 5;

    for (int r = ty; r < 32; r += 8) {
        float v = 0.f;
        const int j = j0 + r, i = i0 + tx;
        if (j < R && i < C) v = src[(size_t)j * C + i];
        tile[r][tx] = v;
    }
    __syncthreads();
    for (int r = ty; r < 32; r += 8) {
        const int i = i0 + r, j = j0 + tx;
        if (i < Dr && j < Dc)
            dst[(size_t)i * Dc + j] = __float2half_rn(tile[tx][r]);
    }
}

// ---------------- HMMA TN GEMM, templated M-tile, 3-stage, split-K ----------------
template <bool OUTH, int MT>
__global__ void __launch_bounds__(256, 2) gemm_f16(
    const __half* __restrict__ A, const __half* __restrict__ Bw,
    const float* __restrict__ bias,
    float* __restrict__ C, __half* __restrict__ Ch,
    int M, int Nn, int K, int nchz)
{
    constexpr int TOFF_B = MT * 128;
    constexpr int TSTAGE = TOFF_B + 16384;
    constexpr int MW  = MT / 32;
    constexpr int NWN = 8 / MW;
    constexpr int NSL = 128 / NWN;
    constexpr int NS  = NSL / 8;
    constexpr int TPR = 256 / MT;
    constexpr int APT = MT / 32;

    const int z = blockIdx.z;
    const int ch0 = z * nchz;
    const int nch = min(nchz, K / 64 - ch0);
    if (nch <= 0) return;
    A  += ch0 * 64;
    Bw += ch0 * 64;
    const bool dob = (z == 0);

    extern __shared__ char smem[];
    const uint32_t sbase = smem_u32(smem);
    const int tid = threadIdx.x;
    const int wid = tid >> 5, lid = tid & 31;
    const int m0 = blockIdx.y * MT;
    const int n0 = blockIdx.x * 128;

    const int wm = wid % MW;
    const int wn = wid / MW;

    float acc[2][NS][4];
#pragma unroll
    for (int i = 0; i < 2; i++)
#pragma unroll
        for (int j = 0; j < NS; j++)
#pragma unroll
            for (int q = 0; q < 4; q++) acc[i][j][q] = 0.f;

    const int lrowA = tid / TPR;
    const int ckA0  = (tid % TPR) * APT;
    const int lrowB = tid >> 1;
    const int ckB0  = (tid & 1) * 4;

    auto load_stage = [&](int st, int c) {
        const int k0 = c * 64;
        const uint32_t stb = sbase + st * TSTAGE;
#pragma unroll
        for (int i = 0; i < APT; i++) {
            const int kc = ckA0 + i;
            const uint32_t so = SW128((uint32_t)(lrowA * 128 + kc * 16));
            cp16(stb + so, A + (size_t)(m0 + lrowA) * K + k0 + kc * 8);
        }
#pragma unroll
        for (int i = 0; i < 4; i++) {
            const int kc = ckB0 + i;
            const uint32_t so = SW128((uint32_t)(lrowB * 128 + kc * 16));
            cp16(stb + TOFF_B + so, Bw + (size_t)(n0 + lrowB) * K + k0 + kc * 8);
        }
        cp_commit();
    };

    load_stage(0, 0);
    if (nch > 1) load_stage(1, 1);

    const int lt = lid >> 3;
    const int lr = lid & 7;

    int st = 0;
    for (int c = 0; c < nch; c++) {
        if (c + 1 < nch) asm volatile("cp.async.wait_group 1;");
        else             asm volatile("cp.async.wait_group 0;");
        __syncthreads();

        if (c + 2 < nch) load_stage((st + 2) % 3, c + 2);

        const uint32_t stb = sbase + st * TSTAGE;
#pragma unroll
        for (int kk = 0; kk < 4; kk++) {
            const int kc = kk * 2 + (lt >> 1);
            uint32_t aH[2][4];
#pragma unroll
            for (int mt = 0; mt < 2; mt++) {
                const int row = wm * 32 + mt * 16 + (lt & 1) * 8 + lr;
                const uint32_t so = SW128((uint32_t)(row * 128 + kc * 16));
                ldm4(aH[mt][0], aH[mt][1], aH[mt][2], aH[mt][3], stb + so);
            }
            uint32_t bf[NS][2];
#pragma unroll
            for (int nt = 0; nt < NS / 2; nt++) {
                const int row = wn * NSL + nt * 16 + (lt & 1) * 8 + lr;
                const uint32_t so = SW128((uint32_t)(row * 128 + kc * 16));
                uint32_t q0, q1, q2, q3;
                ldm4(q0, q1, q2, q3, stb + TOFF_B + so);
                bf[nt * 2][0] = q0; bf[nt * 2][1] = q2;
                bf[nt * 2 + 1][0] = q1; bf[nt * 2 + 1][1] = q3;
            }
#pragma unroll
            for (int mt = 0; mt < 2; mt++)
#pragma unroll
                for (int ns = 0; ns < NS; ns++)
                    mma16816(acc[mt][ns], aH[mt], bf[ns]);
        }
        st = (st + 1) % 3;
    }

    float* Cz = C + (size_t)z * M * Nn;
    __half* Chz = Ch + (size_t)z * M * Nn;
    const int gq = lid >> 2;
    const int tq = lid & 3;
#pragma unroll
    for (int mt = 0; mt < 2; mt++) {
#pragma unroll
        for (int ns = 0; ns < NS; ns++) {
            const int col = n0 + wn * NSL + ns * 8 + tq * 2;
            const int r0 = m0 + wm * 32 + mt * 16 + gq;
            if (col < Nn) {
                const float b0 = dob ? bias[col] : 0.f;
                const float b1 = dob ? bias[col + 1] : 0.f;
                if (OUTH) {
                    __half2 v0 = __floats2half2_rn(acc[mt][ns][0] + b0, acc[mt][ns][1] + b1);
                    __half2 v1 = __floats2half2_rn(acc[mt][ns][2] + b0, acc[mt][ns][3] + b1);
                    *reinterpret_cast<__half2*>(Chz + (size_t)r0 * Nn + col)       = v0;
                    *reinterpret_cast<__half2*>(Chz + (size_t)(r0 + 8) * Nn + col) = v1;
                } else {
                    float2 v0 = make_float2(acc[mt][ns][0] + b0, acc[mt][ns][1] + b1);
                    float2 v1 = make_float2(acc[mt][ns][2] + b0, acc[mt][ns][3] + b1);
                    *reinterpret_cast<float2*>(Cz + (size_t)r0 * Nn + col)       = v0;
                    *reinterpret_cast<float2*>(Cz + (size_t)(r0 + 8) * Nn + col) = v1;
                }
            }
        }
    }
}

// ---------------- FUSED gh GEMM + GRU gate (t >= 1), ping-pong h16 ----------------
__global__ void __launch_bounds__(256, 2) gemm_gru_fused(
    const __half* __restrict__ h_in,
    const __half* __restrict__ BwG,
    const float* __restrict__ b_hh,
    const __half* __restrict__ gi_all,
    float* __restrict__ h, __half* __restrict__ h_out, __half* __restrict__ y16,
    int t)
{
    constexpr int TOFF_B = 8192;
    constexpr int TSTAGE = 8192 + 24576;
    constexpr int NCH = HPAD_ / 64;

    extern __shared__ char smem[];
    const uint32_t sbase = smem_u32(smem);
    const int tid = threadIdx.x;
    const int wid = tid >> 5, lid = tid & 31;
    const int jt = blockIdx.x;
    const int m0 = blockIdx.y * 64;

    const __half* Bw = BwG + (size_t)jt * BR_ * HPAD_;

    const int wm = wid & 1;
    const int wj = wid >> 1;

    float acc[2][6][4];
#pragma unroll
    for (int i = 0; i < 2; i++)
#pragma unroll
        for (int j = 0; j < 6; j++)
#pragma unroll
            for (int q = 0; q < 4; q++) acc[i][j][q] = 0.f;

    auto load_stage = [&](int st, int c) {
        const int k0 = c * 64;
        const uint32_t stb = sbase + st * TSTAGE;
#pragma unroll
        for (int i = 0; i < 2; i++) {
            const int o = tid + 256 * i;
            const int row = o >> 3, kc = o & 7;
            const uint32_t so = SW128((uint32_t)(row * 128 + kc * 16));
            cp16(stb + so, h_in + (size_t)(m0 + row) * HPAD_ + k0 + kc * 8);
        }
#pragma unroll
        for (int i = 0; i < 6; i++) {
            const int o = tid + 256 * i;
            const int row = o >> 3, kc = o & 7;
            const uint32_t so = SW128((uint32_t)(row * 128 + kc * 16));
            cp16(stb + TOFF_B + so, Bw + (size_t)row * HPAD_ + k0 + kc * 8);
        }
        cp_commit();
    };

    load_stage(0, 0);
    load_stage(1, 1);

    const int lt = lid >> 3;
    const int lr = lid & 7;

    int st = 0;
    for (int c = 0; c < NCH; c++) {
        if (c + 1 < NCH) asm volatile("cp.async.wait_group 1;");
        else             asm volatile("cp.async.wait_group 0;");
        __syncthreads();

        if (c + 2 < NCH) load_stage((st + 2) % 3, c + 2);

        const uint32_t stb = sbase + st * TSTAGE;
#pragma unroll
        for (int kk = 0; kk < 4; kk++) {
            const int kc = kk * 2 + (lt >> 1);
            uint32_t aH[2][4];
#pragma unroll
            for (int mt = 0; mt < 2; mt++) {
                const int row = wm * 32 + mt * 16 + (lt & 1) * 8 + lr;
                const uint32_t so = SW128((uint32_t)(row * 128 + kc * 16));
                ldm4(aH[mt][0], aH[mt][1], aH[mt][2], aH[mt][3], stb + so);
            }
            uint32_t bf[6][2];
#pragma unroll
            for (int comp = 0; comp < 3; comp++) {
                const int row = comp * 64 + wj * 16 + (lt & 1) * 8 + lr;
                const uint32_t so = SW128((uint32_t)(row * 128 + kc * 16));
                uint32_t q0, q1, q2, q3;
                ldm4(q0, q1, q2, q3, stb + TOFF_B + so);
                bf[comp * 2][0] = q0; bf[comp * 2][1] = q2;
                bf[comp * 2 + 1][0] = q1; bf[comp * 2 + 1][1] = q3;
            }
#pragma unroll
            for (int mt = 0; mt < 2; mt++)
#pragma unroll
                for (int ns = 0; ns < 6; ns++)
                    mma16816(acc[mt][ns], aH[mt], bf[ns]);
        }
        st = (st + 1) % 3;
    }

    const int gq = lid >> 2;
    const int tq = lid & 3;
#pragma unroll
    for (int mt = 0; mt < 2; mt++) {
#pragma unroll
        for (int k = 0; k < 2; k++) {
            const int j = jt * JT_ + wj * 16 + k * 8 + tq * 2;
            if (j >= H_) continue;
            const float br0 = b_hh[j],          br1 = b_hh[j + 1];
            const float bz0 = b_hh[H_ + j],     bz1 = b_hh[H_ + j + 1];
            const float bn0 = b_hh[2 * H_ + j], bn1 = b_hh[2 * H_ + j + 1];
            const int r0 = m0 + wm * 32 + mt * 16 + gq;
#pragma unroll
            for (int rr = 0; rr < 2; rr++) {
                const int row = r0 + rr * 8;
                const __half* gi = gi_all + (size_t)(row * S_ + t) * G3H_;
                const float2 gir = __half22float2(*reinterpret_cast<const __half2*>(gi + j));
                const float2 giz = __half22float2(*reinterpret_cast<const __half2*>(gi + H_ + j));
                const float2 gin = __half22float2(*reinterpret_cast<const __half2*>(gi + 2 * H_ + j));
                const float2 hp  = *reinterpret_cast<const float2*>(h + (size_t)row * H_ + j);

                const float hr0 = acc[mt][0 + k][rr * 2]     + br0;
                const float hr1 = acc[mt][0 + k][rr * 2 + 1] + br1;
                const float hz0 = acc[mt][2 + k][rr * 2]     + bz0;
                const float hz1 = acc[mt][2 + k][rr * 2 + 1] + bz1;
                const float hn0 = acc[mt][4 + k][rr * 2]     + bn0;
                const float hn1 = acc[mt][4 + k][rr * 2 + 1] + bn1;

                const float rg0 = sigm(gir.x + hr0), rg1 = sigm(gir.y + hr1);
                const float zg0 = sigm(giz.x + hz0), zg1 = sigm(giz.y + hz1);
                const float ng0 = tanhf(gin.x + rg0 * hn0), ng1 = tanhf(gin.y + rg1 * hn1);
                const float h0 = (1.f - zg0) * ng0 + zg0 * hp.x;
                const float h1 = (1.f - zg1) * ng1 + zg1 * hp.y;

                *reinterpret_cast<float2*>(h + (size_t)row * H_ + j) = make_float2(h0, h1);
                const __half2 hv = __floats2half2_rn(h0, h1);
                *reinterpret_cast<__half2*>(h_out + (size_t)row * HPAD_ + j) = hv;
                *reinterpret_cast<__half2*>(y16 + (size_t)row * YPAD_ + t * H_ + j) = hv;
            }
        }
    }
}

// ---------------- GRU gate for t=0 only ----------------
__global__ void __launch_bounds__(256) gru_gate0(
    const __half* __restrict__ gi_all, const float* __restrict__ gh_bias,
    float* __restrict__ h, __half* __restrict__ h16, __half* __restrict__ y16)
{
    const int idx2 = blockIdx.x * blockDim.x + threadIdx.x;
    if (idx2 >= B_ * (H_ / 2)) return;
    const int b = idx2 / (H_ / 2);
    const int j = (idx2 % (H_ / 2)) * 2;

    const __half* gi = gi_all + (size_t)(b * S_) * G3H_;
    const float2 ir2 = __half22float2(*reinterpret_cast<const __half2*>(gi + j));
    const float2 iz2 = __half22float2(*reinterpret_cast<const __half2*>(gi + H_ + j));
    const float2 in2 = __half22float2(*reinterpret_cast<const __half2*>(gi + 2 * H_ + j));
    const float2 hr2 = *reinterpret_cast<const float2*>(gh_bias + j);
    const float2 hz2 = *reinterpret_cast<const float2*>(gh_bias + H_ + j);
    const float2 hn2 = *reinterpret_cast<const float2*>(gh_bias + 2 * H_ + j);

    const float r0 = sigm(ir2.x + hr2.x), r1 = sigm(ir2.y + hr2.y);
    const float z0 = sigm(iz2.x + hz2.x), z1 = sigm(iz2.y + hz2.y);
    const float n0 = tanhf(in2.x + r0 * hn2.x), n1 = tanhf(in2.y + r1 * hn2.y);
    const float h0 = (1.f - z0) * n0;
    const float h1 = (1.f - z1) * n1;

    *reinterpret_cast<float2*>(h + (size_t)b * H_ + j) = make_float2(h0, h1);
    const __half2 hv = __floats2half2_rn(h0, h1);
    *reinterpret_cast<__half2*>(h16 + (size_t)b * HPAD_ + j) = hv;
    *reinterpret_cast<__half2*>(y16 + (size_t)b * YPAD_ + j) = hv;
}

// ---------------- partial sums ----------------
__global__ void __launch_bounds__(256) add2h_kernel(
    const float* __restrict__ p, __half* __restrict__ z1)
{
    const int i = blockIdx.x * 256 + threadIdx.x;
    if (i >= B_ * MLP1_) return;
    const size_t st = (size_t)B_ * MLP1_;
    z1[i] = __float2half_rn(p[i] + p[st + i]);
}
__global__ void __launch_bounds__(256) add4_kernel(
    const float* __restrict__ p, float* __restrict__ out)
{
    const int i = blockIdx.x * 256 + threadIdx.x;
    if (i >= B_ * OUTN_) return;
    const size_t st = (size_t)B_ * OUTN_;
    out[i] = p[i] + p[st + i] + p[2 * st + i] + p[3 * st + i];
}

// ---------------- launch ----------------
extern "C" void kernel_launch(void* const* d_in, const int* in_sizes, int n_in,
                              void* d_out, int out_size)
{
    const float* x          = (const float*)d_in[0];
    const int*   edge_index = (const int*)  d_in[1];
    const float* edge_f     = (const float*)d_in[2];
    const float* edge_attr  = (const float*)d_in[3];
    const float* Wx         = (const float*)d_in[4];
    const float* We         = (const float*)d_in[5];
    const float* Wf         = (const float*)d_in[6];
    const float* Wedge      = (const float*)d_in[7];
    const float* w_ih       = (const float*)d_in[8];
    const float* w_hh       = (const float*)d_in[9];
    const float* b_ih       = (const float*)d_in[10];
    const float* b_hh       = (const float*)d_in[11];
    const float* mlp_w1     = (const float*)d_in[12];
    const float* mlp_b1     = (const float*)d_in[13];
    const float* mlp_w2     = (const float*)d_in[14];
    const float* mlp_b2     = (const float*)d_in[15];
    float* out = (float*)d_out;

    __half *p_seq, *p_wih, *p_whhG, *p_w1t, *p_w2t, *p_h16a, *p_h16b, *p_y16, *p_z1, *p_gi;
    float *p_z1f, *p_o4, *p_h;
    cudaGetSymbolAddress((void**)&p_seq,  g_seq16);
    cudaGetSymbolAddress((void**)&p_wih,  g_wih16);
    cudaGetSymbolAddress((void**)&p_whhG, g_whhG);
    cudaGetSymbolAddress((void**)&p_w1t,  g_w1t16);
    cudaGetSymbolAddress((void**)&p_w2t,  g_w2t16);
    cudaGetSymbolAddress((void**)&p_h16a, g_h16a);
    cudaGetSymbolAddress((void**)&p_h16b, g_h16b);
    cudaGetSymbolAddress((void**)&p_y16,  g_y16);
    cudaGetSymbolAddress((void**)&p_z1,   g_z1);
    cudaGetSymbolAddress((void**)&p_gi,   g_gi);
    cudaGetSymbolAddress((void**)&p_z1f,  g_z1f);
    cudaGetSymbolAddress((void**)&p_o4,   g_o4);
    cudaGetSymbolAddress((void**)&p_h,    g_h);

    const int SM64  = 3 * (64 * 128 + 16384);    // 73728
    const int SM128 = 3 * (128 * 128 + 16384);   // 98304
    const int SMFU  = 3 * (8192 + 24576);        // 98304

    cudaFuncSetAttribute((const void*)gemm_f16<true, 128>,
                         cudaFuncAttributeMaxDynamicSharedMemorySize, SM128);
    cudaFuncSetAttribute((const void*)gemm_f16<false, 64>,
                         cudaFuncAttributeMaxDynamicSharedMemorySize, SM64);
    cudaFuncSetAttribute((const void*)gemm_f16<false, 128>,
                         cudaFuncAttributeMaxDynamicSharedMemorySize, SM128);
    cudaFuncSetAttribute((const void*)gemm_gru_fused,
                         cudaFuncAttributeMaxDynamicSharedMemorySize, SMFU);

    // streams + events (host-side, created once; no device alloc)
    static cudaStream_t s1 = nullptr, s2 = nullptr;
    static cudaEvent_t evFork = nullptr, evJoin = nullptr, evG[NCHK_];
    if (s1 == nullptr) {
        cudaStreamCreateWithFlags(&s1, cudaStreamNonBlocking);
        cudaStreamCreateWithFlags(&s2, cudaStreamNonBlocking);
        cudaEventCreateWithFlags(&evFork, cudaEventDisableTiming);
        cudaEventCreateWithFlags(&evJoin, cudaEventDisableTiming);
        for (int c = 0; c < NCHK_; c++)
            cudaEventCreateWithFlags(&evG[c], cudaEventDisableTiming);
    }

    // fork
    cudaEventRecord(evFork, 0);
    cudaStreamWaitEvent(s1, evFork, 0);
    cudaStreamWaitEvent(s2, evFork, 0);

    // s1: memsets + weight conversions
    cudaMemsetAsync(p_h16a, 0, sizeof(__half) * B_ * HPAD_, s1);
    cudaMemsetAsync(p_h16b, 0, sizeof(__half) * B_ * HPAD_, s1);
    cudaMemsetAsync(p_y16, 0, sizeof(__half) * B_ * YPAD_, s1);
    conv_direct<<<NB_CV, 256, 0, s1>>>(w_ih, w_hh, p_wih, p_whhG);
    {
        dim3 gt1((YPAD_ + 31) / 32, MLP1_ / 32);
        trans_conv<<<gt1, 256, 0, s1>>>(mlp_w1, p_w1t, S_ * H_, MLP1_, MLP1_, YPAD_);
        dim3 gt2((MLP1_ + 31) / 32, OUTNP_ / 32);
        trans_conv<<<gt2, 256, 0, s1>>>(mlp_w2, p_w2t, MLP1_, OUTN_, OUTNP_, MLP1_);
    }
    cudaEventRecord(evJoin, s1);

    // s2: GNN in 2 chunks, event per chunk
    for (int c = 0; c < NCHK_; c++) {
        gnn_kernel<<<CHG_, 256, 0, s2>>>(x, edge_index, edge_f, edge_attr,
                                         Wx, We, Wf, Wedge, p_seq, c * CHG_);
        cudaEventRecord(evG[c], s2);
    }

    // stream 0: gi chunk-by-chunk (760-CTA chunks: same total rounds as unchunked)
    cudaStreamWaitEvent(0, evJoin, 0);
    for (int c = 0; c < NCHK_; c++) {
        cudaStreamWaitEvent(0, evG[c], 0);
        dim3 grid(G3HP_ / 128, CHG_ / 128, 1);   // 19 x 40
        gemm_f16<true, 128><<<grid, 256, SM128>>>(
            p_seq + (size_t)c * CHG_ * SEQ_, p_wih, b_ih,
            nullptr, p_gi + (size_t)c * CHG_ * G3H_, CHG_, G3H_, SEQ_, 84);
    }

    // 3) GRU: t=0 pointwise -> h16a; t>=1 fused with ping-pong h16 buffers
    gru_gate0<<<(B_ * (H_ / 2) + 255) / 256, 256>>>(p_gi, b_hh, p_h, p_h16a, p_y16);
    {
        dim3 gridf(NJT_, B_ / 64);              // 13 x 32
        __half* bufs[2] = { p_h16a, p_h16b };
        for (int t = 1; t < S_; t++) {
            __half* hin  = bufs[(t - 1) & 1];
            __half* hout = bufs[t & 1];
            gemm_gru_fused<<<gridf, 256, SMFU>>>(hin, p_whhG, b_hh, p_gi,
                                                 p_h, hout, p_y16, t);
        }
    }

    // 4) MLP
    {
        dim3 g1(MLP1_ / 128, B_ / 64, 2);       // mlp1: MT=64, split-K=2
        gemm_f16<false, 64><<<g1, 256, SM64>>>(p_y16, p_w1t, mlp_b1,
                                               p_z1f, nullptr, B_, MLP1_, YPAD_, 32);
        add2h_kernel<<<(B_ * MLP1_ + 255) / 256, 256>>>(p_z1f, p_z1);

        dim3 g2(OUTNP_ / 128, B_ / 128, 4);     // mlp2: MT=128, split-K=4
        gemm_f16<false, 128><<<g2, 256, SM128>>>(p_z1, p_w2t, mlp_b2,
                                                 p_o4, nullptr, B_, OUTN_, MLP1_, 5);
        add4_kernel<<<(B_ * OUTN_ + 255) / 256, 256>>>(p_o4, out);
    }
}